// round 10
// baseline (speedup 1.0000x reference)
#include <cuda_runtime.h>
#include <cstdint>

// ---------------------------------------------------------------------------
// GIN: 3 layers of { rst = h + segment_sum(h[src], dst); h = MLP2(rst) }
// N=100000, E=1600000, D=128.
//   - CSR build (3 launches): hist, single-block scan, fill(+deg re-zero)
//   - PERSISTENT fused layer kernel, 1 block/SM, 512 threads:
//       warps 0-7  = producers: gather tile into double-buffered smem
//       warps 8-15 = consumers: FFMA2 (fma.rn.f32x2) 2-GEMM MLP
//     Named-barrier full/empty handshake -> gather overlaps GEMM.
//     W1+W2 loaded once per kernel (resident in smem).
//   - Last layer: no relu anywhere -> folded single GEMM with
//     W12 = W1@W2, b12 = b1@W2 + b2.
// ---------------------------------------------------------------------------

#define DIM 128
#define MAXN 100000
#define MAXE 1600000
#define TILE_M 64
#define SA_PITCH 132
#define SMEM_FLOATS (2 * 16384 + 2 * TILE_M * SA_PITCH)
#define SMEM_BYTES (SMEM_FLOATS * 4)

#define BAR_FULL0  1
#define BAR_FULL1  2
#define BAR_EMPTY0 3
#define BAR_EMPTY1 4
#define BAR_CONS   5

typedef unsigned long long u64;

// scratch (device globals: no allocation allowed; zero-initialized at load)
__device__ int   g_deg[MAXN];
__device__ int   g_rowptr[MAXN + 1];
__device__ int   g_cursor[MAXN];
__device__ int   g_col[MAXE];
__device__ __align__(16) float g_hA [(size_t)MAXN * DIM];
__device__ __align__(16) float g_hB [(size_t)MAXN * DIM];
__device__ __align__(16) float g_W12[DIM * DIM];
__device__ __align__(16) float g_b12[DIM];

// ------------------------- helpers ------------------------------------------

__device__ __forceinline__ u64 pack2(float x, float y) {
    u64 r;
    asm("mov.b64 %0, {%1, %2};" : "=l"(r) : "f"(x), "f"(y));
    return r;
}
__device__ __forceinline__ void unpack2(u64 v, float& x, float& y) {
    asm("mov.b64 {%0, %1}, %2;" : "=f"(x), "=f"(y) : "l"(v));
}
__device__ __forceinline__ void fma2(u64& d, u64 a, u64 b) {
    asm("fma.rn.f32x2 %0, %1, %2, %0;" : "+l"(d) : "l"(a), "l"(b));
}
__device__ __forceinline__ void bar_sync(int id, int cnt) {
    asm volatile("bar.sync %0, %1;" :: "r"(id), "r"(cnt) : "memory");
}
__device__ __forceinline__ void bar_arrive(int id, int cnt) {
    asm volatile("bar.arrive %0, %1;" :: "r"(id), "r"(cnt) : "memory");
}

// -------------------------- CSR build ---------------------------------------

__global__ void k_hist(const int* __restrict__ dst, int e) {
    int i = blockIdx.x * blockDim.x + threadIdx.x;
    if (i < e) atomicAdd(&g_deg[dst[i]], 1);
}

// single-block exclusive scan of g_deg -> g_rowptr / g_cursor
__global__ void __launch_bounds__(1024) k_scan1(int n, int e) {
    __shared__ int s[1024];
    const int tid = threadIdx.x;
    int carry = 0;
    const int CH = 1024 * 8;
    for (int base = 0; base < n; base += CH) {
        int v[8];
        int run = 0;
#pragma unroll
        for (int j = 0; j < 8; ++j) {
            int idx = base + tid * 8 + j;
            int t = (idx < n) ? g_deg[idx] : 0;
            v[j] = run;
            run += t;
        }
        s[tid] = run;
        __syncthreads();
        int tot = run;
        for (int off = 1; off < 1024; off <<= 1) {
            int add = (tid >= off) ? s[tid - off] : 0;
            __syncthreads();
            s[tid] += add;
            __syncthreads();
        }
        int excl = carry + s[tid] - tot;
#pragma unroll
        for (int j = 0; j < 8; ++j) {
            int idx = base + tid * 8 + j;
            if (idx < n) {
                int r = excl + v[j];
                g_rowptr[idx] = r;
                g_cursor[idx] = r;
            }
        }
        carry += s[1023];
        __syncthreads();
    }
    if (tid == 0) g_rowptr[n] = e;
}

// bucket fill; also re-zeroes g_deg for the next graph replay
__global__ void k_fill(const int* __restrict__ src, const int* __restrict__ dst,
                       int e, int n) {
    int i = blockIdx.x * blockDim.x + threadIdx.x;
    if (i < n) g_deg[i] = 0;
    if (i < e) {
        int d = dst[i];
        int pos = atomicAdd(&g_cursor[d], 1);
        g_col[pos] = src[i];
    }
}

// -------------------- last-layer weight folding ------------------------------
// blocks 0..127: W12[k][n] = sum_j W1[k][j]*W2[j][n]
// block 128:     b12[n]    = sum_j b1[j]*W2[j][n] + b2[n]

__global__ void k_wbfuse(const float* __restrict__ W1g, const float* __restrict__ W2g,
                         const float* __restrict__ b1g, const float* __restrict__ b2g) {
    __shared__ float row[128];
    int nn = threadIdx.x;
    if (blockIdx.x < 128) {
        int k = blockIdx.x;
        row[nn] = W1g[k * 128 + nn];
        __syncthreads();
        float acc = 0.f;
#pragma unroll 8
        for (int j = 0; j < 128; ++j) acc += row[j] * W2g[j * 128 + nn];
        g_W12[k * 128 + nn] = acc;
    } else {
        row[nn] = b1g[nn];
        __syncthreads();
        float acc = b2g[nn];
#pragma unroll 8
        for (int j = 0; j < 128; ++j) acc += row[j] * W2g[j * 128 + nn];
        g_b12[nn] = acc;
    }
}

// ---------------------- consumer GEMM phase ----------------------------------
// 64x128x128, 256 consumer threads, thread tile 4 rows x 8 cols,
// accumulators as 16 packed f32x2 (4 col-pairs per row).

__device__ __forceinline__ void gemm64(const float* __restrict__ sA,
                                       const float* __restrict__ sW,
                                       const u64 bb[4], int r0, int c0,
                                       u64 acc[4][4]) {
#pragma unroll
    for (int i = 0; i < 4; ++i)
#pragma unroll
        for (int j = 0; j < 4; ++j) acc[i][j] = bb[j];
#pragma unroll 1
    for (int k0 = 0; k0 < 128; k0 += 4) {
        float4 a4[4];
#pragma unroll
        for (int i = 0; i < 4; ++i)
            a4[i] = *(const float4*)&sA[(r0 + i) * SA_PITCH + k0];
#pragma unroll
        for (int kk = 0; kk < 4; ++kk) {
            ulonglong2 w0 = *(const ulonglong2*)&sW[(k0 + kk) * 128 + c0];
            ulonglong2 w1 = *(const ulonglong2*)&sW[(k0 + kk) * 128 + c0 + 4];
#pragma unroll
            for (int i = 0; i < 4; ++i) {
                float av = ((const float*)&a4[i])[kk];
                u64 aa = pack2(av, av);
                fma2(acc[i][0], aa, w0.x);
                fma2(acc[i][1], aa, w0.y);
                fma2(acc[i][2], aa, w1.x);
                fma2(acc[i][3], aa, w1.y);
            }
        }
    }
}

// ---------------------- persistent fused layer -------------------------------
// LAST=false: out = relu( relu(A@W1+b1) @ W2 + b2 )
// LAST=true : out = A@W1+b1   (W1 = folded W12, b1 = folded b12)

template <bool LAST>
__global__ void __launch_bounds__(512, 1)
k_gin(const float* __restrict__ hin,
      const float* __restrict__ W1g, const float* __restrict__ b1g,
      const float* __restrict__ W2g, const float* __restrict__ b2g,
      float* __restrict__ out, int n, int T) {
    extern __shared__ float smem[];
    float* sW1 = smem;             // 16384
    float* sW2 = smem + 16384;     // 16384
    float* sAb = smem + 32768;     // 2 * 64*SA_PITCH

    const int tid = threadIdx.x;
    const int G = gridDim.x;

    // load weights once per kernel (all 512 threads)
    {
        const float4* w4 = (const float4*)W1g;
        float4* s4 = (float4*)sW1;
#pragma unroll
        for (int it = 0; it < 8; ++it) s4[tid + it * 512] = w4[tid + it * 512];
        if (!LAST) {
            const float4* v4 = (const float4*)W2g;
            float4* t4 = (float4*)sW2;
#pragma unroll
            for (int it = 0; it < 8; ++it) t4[tid + it * 512] = v4[tid + it * 512];
        }
    }
    __syncthreads();

    if (tid < 256) {
        // ================= producer: gather tiles ==========================
        const int wid = tid >> 5, lane = tid & 31;
        const float4* __restrict__ h4 = (const float4*)hin;
        int s = 0;
        for (int t = blockIdx.x; t < T; t += G, ++s) {
            const int buf = s & 1;
            if (s >= 2) bar_sync(BAR_EMPTY0 + buf, 512);
            float* sA = sAb + buf * (TILE_M * SA_PITCH);
            const int row0 = t * TILE_M;
#pragma unroll 1
            for (int rr = 0; rr < 8; ++rr) {
                int r  = wid * 8 + rr;
                int rg = row0 + r;
                float4 a = make_float4(0.f, 0.f, 0.f, 0.f);
                if (rg < n) {
                    a = h4[(size_t)rg * 32 + lane];   // self, (1+eps)=1
                    int i = g_rowptr[rg];
                    const int epos = g_rowptr[rg + 1];
                    for (; i + 8 <= epos; i += 8) {
                        int s0 = g_col[i],     s1 = g_col[i + 1];
                        int s2 = g_col[i + 2], s3 = g_col[i + 3];
                        int s4_ = g_col[i + 4], s5 = g_col[i + 5];
                        int s6 = g_col[i + 6], s7 = g_col[i + 7];
                        float4 v0 = __ldg(&h4[(size_t)s0 * 32 + lane]);
                        float4 v1 = __ldg(&h4[(size_t)s1 * 32 + lane]);
                        float4 v2 = __ldg(&h4[(size_t)s2 * 32 + lane]);
                        float4 v3 = __ldg(&h4[(size_t)s3 * 32 + lane]);
                        float4 v4 = __ldg(&h4[(size_t)s4_ * 32 + lane]);
                        float4 v5 = __ldg(&h4[(size_t)s5 * 32 + lane]);
                        float4 v6 = __ldg(&h4[(size_t)s6 * 32 + lane]);
                        float4 v7 = __ldg(&h4[(size_t)s7 * 32 + lane]);
                        float4 p0, p1, p2, p3;
                        p0.x = v0.x + v1.x; p0.y = v0.y + v1.y; p0.z = v0.z + v1.z; p0.w = v0.w + v1.w;
                        p1.x = v2.x + v3.x; p1.y = v2.y + v3.y; p1.z = v2.z + v3.z; p1.w = v2.w + v3.w;
                        p2.x = v4.x + v5.x; p2.y = v4.y + v5.y; p2.z = v4.z + v5.z; p2.w = v4.w + v5.w;
                        p3.x = v6.x + v7.x; p3.y = v6.y + v7.y; p3.z = v6.z + v7.z; p3.w = v6.w + v7.w;
                        a.x += (p0.x + p1.x) + (p2.x + p3.x);
                        a.y += (p0.y + p1.y) + (p2.y + p3.y);
                        a.z += (p0.z + p1.z) + (p2.z + p3.z);
                        a.w += (p0.w + p1.w) + (p2.w + p3.w);
                    }
                    if (i + 4 <= epos) {
                        int s0 = g_col[i],     s1 = g_col[i + 1];
                        int s2 = g_col[i + 2], s3 = g_col[i + 3];
                        float4 v0 = __ldg(&h4[(size_t)s0 * 32 + lane]);
                        float4 v1 = __ldg(&h4[(size_t)s1 * 32 + lane]);
                        float4 v2 = __ldg(&h4[(size_t)s2 * 32 + lane]);
                        float4 v3 = __ldg(&h4[(size_t)s3 * 32 + lane]);
                        a.x += (v0.x + v1.x) + (v2.x + v3.x);
                        a.y += (v0.y + v1.y) + (v2.y + v3.y);
                        a.z += (v0.z + v1.z) + (v2.z + v3.z);
                        a.w += (v0.w + v1.w) + (v2.w + v3.w);
                        i += 4;
                    }
                    for (; i < epos; ++i) {
                        int sn = g_col[i];
                        float4 v = __ldg(&h4[(size_t)sn * 32 + lane]);
                        a.x += v.x; a.y += v.y; a.z += v.z; a.w += v.w;
                    }
                }
                *(float4*)&sA[r * SA_PITCH + lane * 4] = a;
            }
            __threadfence_block();
            bar_arrive(BAR_FULL0 + buf, 512);
        }
    } else {
        // ================= consumer: 2-GEMM MLP ============================
        const int tc   = tid - 256;
        const int trow = tc >> 4;     // 0..15 -> rows trow*4..+3
        const int tcol = tc & 15;     // 0..15 -> cols tcol*8..+7
        const int r0 = trow * 4, c0 = tcol * 8;

        u64 bb1[4], bb2[4];
        {
            float4 x = *(const float4*)&b1g[c0];
            float4 y = *(const float4*)&b1g[c0 + 4];
            bb1[0] = pack2(x.x, x.y); bb1[1] = pack2(x.z, x.w);
            bb1[2] = pack2(y.x, y.y); bb1[3] = pack2(y.z, y.w);
            if (!LAST) {
                float4 u = *(const float4*)&b2g[c0];
                float4 v = *(const float4*)&b2g[c0 + 4];
                bb2[0] = pack2(u.x, u.y); bb2[1] = pack2(u.z, u.w);
                bb2[2] = pack2(v.x, v.y); bb2[3] = pack2(v.z, v.w);
            }
        }

        int s = 0;
        for (int t = blockIdx.x; t < T; t += G, ++s) {
            const int buf = s & 1;
            bar_sync(BAR_FULL0 + buf, 512);
            float* sA = sAb + buf * (TILE_M * SA_PITCH);
            const int row0 = t * TILE_M;

            u64 acc[4][4];
            gemm64(sA, sW1, bb1, r0, c0, acc);

            if (!LAST) {
                // all consumers must finish reading A before h1 overwrites it
                bar_sync(BAR_CONS, 256);
#pragma unroll
                for (int i = 0; i < 4; ++i) {
                    float4 o0, o1;
                    unpack2(acc[i][0], o0.x, o0.y);
                    unpack2(acc[i][1], o0.z, o0.w);
                    unpack2(acc[i][2], o1.x, o1.y);
                    unpack2(acc[i][3], o1.z, o1.w);
                    o0.x = fmaxf(o0.x, 0.f); o0.y = fmaxf(o0.y, 0.f);
                    o0.z = fmaxf(o0.z, 0.f); o0.w = fmaxf(o0.w, 0.f);
                    o1.x = fmaxf(o1.x, 0.f); o1.y = fmaxf(o1.y, 0.f);
                    o1.z = fmaxf(o1.z, 0.f); o1.w = fmaxf(o1.w, 0.f);
                    *(float4*)&sA[(r0 + i) * SA_PITCH + c0]     = o0;
                    *(float4*)&sA[(r0 + i) * SA_PITCH + c0 + 4] = o1;
                }
                bar_sync(BAR_CONS, 256);

                u64 acc2[4][4];
                gemm64(sA, sW2, bb2, r0, c0, acc2);
                bar_arrive(BAR_EMPTY0 + buf, 512);   // buffer free for producer

#pragma unroll
                for (int i = 0; i < 4; ++i) {
                    int rg = row0 + r0 + i;
                    if (rg < n) {
                        float4 o0, o1;
                        unpack2(acc2[i][0], o0.x, o0.y);
                        unpack2(acc2[i][1], o0.z, o0.w);
                        unpack2(acc2[i][2], o1.x, o1.y);
                        unpack2(acc2[i][3], o1.z, o1.w);
                        o0.x = fmaxf(o0.x, 0.f); o0.y = fmaxf(o0.y, 0.f);
                        o0.z = fmaxf(o0.z, 0.f); o0.w = fmaxf(o0.w, 0.f);
                        o1.x = fmaxf(o1.x, 0.f); o1.y = fmaxf(o1.y, 0.f);
                        o1.z = fmaxf(o1.z, 0.f); o1.w = fmaxf(o1.w, 0.f);
                        *(float4*)&out[(size_t)rg * 128 + c0]     = o0;
                        *(float4*)&out[(size_t)rg * 128 + c0 + 4] = o1;
                    }
                }
            } else {
                bar_arrive(BAR_EMPTY0 + buf, 512);
#pragma unroll
                for (int i = 0; i < 4; ++i) {
                    int rg = row0 + r0 + i;
                    if (rg < n) {
                        float4 o0, o1;
                        unpack2(acc[i][0], o0.x, o0.y);
                        unpack2(acc[i][1], o0.z, o0.w);
                        unpack2(acc[i][2], o1.x, o1.y);
                        unpack2(acc[i][3], o1.z, o1.w);
                        *(float4*)&out[(size_t)rg * 128 + c0]     = o0;
                        *(float4*)&out[(size_t)rg * 128 + c0 + 4] = o1;
                    }
                }
            }
        }
    }
}

// ---------------------------- host ------------------------------------------

extern "C" void kernel_launch(void* const* d_in, const int* in_sizes, int n_in,
                              void* d_out, int out_size) {
    const float* feat = (const float*)d_in[0];
    const float* W1   = (const float*)d_in[1];
    const float* b1   = (const float*)d_in[2];
    const float* W2   = (const float*)d_in[3];
    const float* b2   = (const float*)d_in[4];
    const int*   src  = (const int*)d_in[5];
    const int*   dst  = (const int*)d_in[6];

    const int n = in_sizes[0] / DIM;
    const int e = in_sizes[5];

    cudaFuncSetAttribute((const void*)k_gin<false>,
                         cudaFuncAttributeMaxDynamicSharedMemorySize, SMEM_BYTES);
    cudaFuncSetAttribute((const void*)k_gin<true>,
                         cudaFuncAttributeMaxDynamicSharedMemorySize, SMEM_BYTES);

    int G = 148;
    cudaDeviceGetAttribute(&G, cudaDevAttrMultiProcessorCount, 0);

    float *hA, *hB, *w12, *b12;
    cudaGetSymbolAddress((void**)&hA,  g_hA);
    cudaGetSymbolAddress((void**)&hB,  g_hB);
    cudaGetSymbolAddress((void**)&w12, g_W12);
    cudaGetSymbolAddress((void**)&b12, g_b12);

    const int T = (n + TILE_M - 1) / TILE_M;

    // ---- CSR build (g_deg is zero at load and re-zeroed by k_fill) ----
    k_hist<<<(e + 255) / 256, 256>>>(dst, e);                 // launch 0
    k_scan1<<<1, 1024>>>(n, e);                               // launch 1
    k_fill<<<(e + 255) / 256, 256>>>(src, dst, e, n);         // launch 2

    // ---- layer 0 ----                                        launch 3
    k_gin<false><<<G, 512, SMEM_BYTES>>>(
        feat, W1 + 0 * DIM * DIM, b1 + 0 * DIM, W2 + 0 * DIM * DIM, b2 + 0 * DIM,
        hA, n, T);
    // ---- layer 1 ----                                        launch 4
    k_gin<false><<<G, 512, SMEM_BYTES>>>(
        hA, W1 + 1 * DIM * DIM, b1 + 1 * DIM, W2 + 1 * DIM * DIM, b2 + 1 * DIM,
        hB, n, T);
    // ---- fold last-layer weights ----                        launch 5
    k_wbfuse<<<129, 128>>>(W1 + 2 * DIM * DIM, W2 + 2 * DIM * DIM,
                           b1 + 2 * DIM, b2 + 2 * DIM);
    // ---- layer 2 (folded single GEMM, no relu) ----          launch 6
    k_gin<true><<<G, 512, SMEM_BYTES>>>(
        hB, w12, b12, nullptr, nullptr, (float*)d_out, n, T);
}